// round 1
// baseline (speedup 1.0000x reference)
#include <cuda_runtime.h>

#define TSEQ 2048
#define NB   2
#define NH   16
#define HDIM 64
#define CDIM 1024

// Scratch (device globals: allocation-free, graph-safe)
__device__ float g_Q[(size_t)NB * NH * TSEQ * HDIM];   // [B,H,T,HD]
__device__ float g_K[(size_t)NB * NH * TSEQ * HDIM];
__device__ float g_V[(size_t)NB * NH * TSEQ * HDIM];
__device__ float g_Y[(size_t)NB * TSEQ * CDIM];        // [B,T,C]

// ---------------------------------------------------------------------------
// Tiled fp32 GEMM: C = A[M,1024] @ W[1024,N] + bias
// MODE 0: scatter into g_Q/g_K/g_V ([B,H,T,HD]); MODE 1: write to `out` row-major
// 128x128 block tile, BK=16, 256 threads, 8x8 per thread.
// ---------------------------------------------------------------------------
template <int N, int MODE>
__launch_bounds__(256)
__global__ void gemm_kernel(const float* __restrict__ A,
                            const float* __restrict__ W,
                            const float* __restrict__ bias,
                            float* __restrict__ out)
{
    __shared__ float As[16][128];
    __shared__ float Bs[16][128];
    const int tid = threadIdx.x;
    const int m0 = blockIdx.y * 128;
    const int n0 = blockIdx.x * 128;
    const int ty = tid >> 4, tx = tid & 15;

    float acc[8][8];
#pragma unroll
    for (int i = 0; i < 8; i++)
#pragma unroll
        for (int j = 0; j < 8; j++) acc[i][j] = 0.f;

    for (int k0 = 0; k0 < CDIM; k0 += 16) {
#pragma unroll
        for (int u = 0; u < 2; u++) {
            int idx = tid * 2 + u;                    // 0..511 (float4 granularity)
            // A tile: 128 rows x 16 k, stored k-major
            int m = idx >> 2, kk = idx & 3;
            float4 va = *(const float4*)(A + (size_t)(m0 + m) * CDIM + k0 + kk * 4);
            As[kk * 4 + 0][m] = va.x;
            As[kk * 4 + 1][m] = va.y;
            As[kk * 4 + 2][m] = va.z;
            As[kk * 4 + 3][m] = va.w;
            // B tile: 16 k x 128 n, direct copy
            int kb = idx >> 5, n4 = idx & 31;
            *(float4*)&Bs[kb][n4 * 4] =
                *(const float4*)(W + (size_t)(k0 + kb) * N + n0 + n4 * 4);
        }
        __syncthreads();
#pragma unroll
        for (int k = 0; k < 16; k++) {
            float a[8], b[8];
            *(float4*)(a)     = *(const float4*)&As[k][ty * 8];
            *(float4*)(a + 4) = *(const float4*)&As[k][ty * 8 + 4];
            *(float4*)(b)     = *(const float4*)&Bs[k][tx * 8];
            *(float4*)(b + 4) = *(const float4*)&Bs[k][tx * 8 + 4];
#pragma unroll
            for (int i = 0; i < 8; i++)
#pragma unroll
                for (int j = 0; j < 8; j++)
                    acc[i][j] = fmaf(a[i], b[j], acc[i][j]);
        }
        __syncthreads();
    }

#pragma unroll
    for (int i = 0; i < 8; i++) {
        int m = m0 + ty * 8 + i;
#pragma unroll
        for (int j = 0; j < 8; j++) {
            int n = n0 + tx * 8 + j;
            float v = acc[i][j] + bias[n];
            if (MODE == 0) {
                int seg = n >> 10;            // 0=Q, 1=K, 2=V
                int c = n & 1023;
                int h = c >> 6, d = c & 63;
                int b = m >> 11, t = m & 2047;
                size_t oi = (((size_t)b * NH + h) * TSEQ + t) * HDIM + d;
                float* dst = (seg == 0) ? g_Q : (seg == 1) ? g_K : g_V;
                dst[oi] = v;
            } else {
                out[(size_t)m * N + n] = v;
            }
        }
    }
}

// ---------------------------------------------------------------------------
// Flash-style causal attention, fp32.
// One block = (batch*head, 64-row Q tile). 256 threads (16x16), 4x4 per thread.
// Smem: Qs (plain), KP (K tile / later P tile, float4-XOR-swizzled),
//       Vt (V transposed, swizzled). 48 KB total.
// ---------------------------------------------------------------------------
__launch_bounds__(256)
__global__ void attn_kernel()
{
    __shared__ float Qs[64 * 64];
    __shared__ float KP[64 * 64];
    __shared__ float Vt[64 * 64];

    const int tid = threadIdx.x;
    const int ty = tid >> 4, tx = tid & 15;
    const int bh = blockIdx.y;
    const int q0 = blockIdx.x * 64;
    const float* Qg = g_Q + (size_t)bh * TSEQ * HDIM;
    const float* Kg = g_K + (size_t)bh * TSEQ * HDIM;
    const float* Vg = g_V + (size_t)bh * TSEQ * HDIM;

    // Load Q tile, pre-scaled by 1/sqrt(HD) = 0.125
#pragma unroll
    for (int u = 0; u < 4; u++) {
        int idx = tid + u * 256;          // float4 index 0..1023
        int r = idx >> 4, c4 = idx & 15;
        float4 q = *(const float4*)&Qg[(size_t)(q0 + r) * HDIM + c4 * 4];
        q.x *= 0.125f; q.y *= 0.125f; q.z *= 0.125f; q.w *= 0.125f;
        *(float4*)&Qs[r * 64 + c4 * 4] = q;
    }

    float o[4][4];
    float mr[4], lr[4];
#pragma unroll
    for (int i = 0; i < 4; i++) {
        mr[i] = -1e30f; lr[i] = 0.f;
#pragma unroll
        for (int j = 0; j < 4; j++) o[i][j] = 0.f;
    }

    const int r0 = ty * 4;   // q-row offset within tile
    const int c0 = tx * 4;   // k-col / head-dim-col offset within tile
    const int nkt = blockIdx.x + 1;       // causal: only tiles with k0 <= q0

    for (int kt = 0; kt < nkt; kt++) {
        const int k0 = kt * 64;
        __syncthreads();  // previous iteration's KP/Vt reads (and Qs store) done
        // Load K tile (row-swizzled) and V tile transposed (swizzled)
#pragma unroll
        for (int u = 0; u < 4; u++) {
            int idx = tid + u * 256;
            int r = idx >> 4, c4 = idx & 15;
            float4 kv = *(const float4*)&Kg[(size_t)(k0 + r) * HDIM + c4 * 4];
            *(float4*)&KP[r * 64 + ((c4 ^ (r & 15)) * 4)] = kv;
            float4 vv = *(const float4*)&Vg[(size_t)(k0 + r) * HDIM + c4 * 4];
            int k4 = r >> 2, kin = r & 3;
            {
                int d = c4 * 4 + 0; Vt[d * 64 + ((k4 ^ (d & 15)) * 4 + kin)] = vv.x;
            }
            {
                int d = c4 * 4 + 1; Vt[d * 64 + ((k4 ^ (d & 15)) * 4 + kin)] = vv.y;
            }
            {
                int d = c4 * 4 + 2; Vt[d * 64 + ((k4 ^ (d & 15)) * 4 + kin)] = vv.z;
            }
            {
                int d = c4 * 4 + 3; Vt[d * 64 + ((k4 ^ (d & 15)) * 4 + kin)] = vv.w;
            }
        }
        __syncthreads();

        // S = (Q/8) @ K^T
        float s[4][4];
#pragma unroll
        for (int i = 0; i < 4; i++)
#pragma unroll
            for (int j = 0; j < 4; j++) s[i][j] = 0.f;
#pragma unroll
        for (int d4 = 0; d4 < 16; d4++) {
            float4 q4[4], k4v[4];
#pragma unroll
            for (int i = 0; i < 4; i++)
                q4[i] = *(const float4*)&Qs[(r0 + i) * 64 + d4 * 4];
#pragma unroll
            for (int j = 0; j < 4; j++) {
                int c = c0 + j;
                k4v[j] = *(const float4*)&KP[c * 64 + ((d4 ^ (c & 15)) * 4)];
            }
#pragma unroll
            for (int i = 0; i < 4; i++)
#pragma unroll
                for (int j = 0; j < 4; j++) {
                    s[i][j] = fmaf(q4[i].x, k4v[j].x, s[i][j]);
                    s[i][j] = fmaf(q4[i].y, k4v[j].y, s[i][j]);
                    s[i][j] = fmaf(q4[i].z, k4v[j].z, s[i][j]);
                    s[i][j] = fmaf(q4[i].w, k4v[j].w, s[i][j]);
                }
        }

        // Causal mask only on the diagonal tile
        if (kt == nkt - 1) {
#pragma unroll
            for (int i = 0; i < 4; i++)
#pragma unroll
                for (int j = 0; j < 4; j++)
                    if (k0 + c0 + j > q0 + r0 + i) s[i][j] = -1e30f;
        }

        // Online softmax (row reduce over the 16 tx lanes of each half-warp)
        float p[4][4];
#pragma unroll
        for (int i = 0; i < 4; i++) {
            float rm = fmaxf(fmaxf(s[i][0], s[i][1]), fmaxf(s[i][2], s[i][3]));
            rm = fmaxf(rm, __shfl_xor_sync(0xffffffffu, rm, 8));
            rm = fmaxf(rm, __shfl_xor_sync(0xffffffffu, rm, 4));
            rm = fmaxf(rm, __shfl_xor_sync(0xffffffffu, rm, 2));
            rm = fmaxf(rm, __shfl_xor_sync(0xffffffffu, rm, 1));
            float mn = fmaxf(mr[i], rm);
            float alpha = __expf(mr[i] - mn);
            mr[i] = mn;
            float rs = 0.f;
#pragma unroll
            for (int j = 0; j < 4; j++) {
                p[i][j] = __expf(s[i][j] - mn);
                rs += p[i][j];
            }
            rs += __shfl_xor_sync(0xffffffffu, rs, 8);
            rs += __shfl_xor_sync(0xffffffffu, rs, 4);
            rs += __shfl_xor_sync(0xffffffffu, rs, 2);
            rs += __shfl_xor_sync(0xffffffffu, rs, 1);
            lr[i] = lr[i] * alpha + rs;
#pragma unroll
            for (int j = 0; j < 4; j++) o[i][j] *= alpha;
        }

        __syncthreads();  // all threads finished reading KP as K-tile
        // Store P into KP (same swizzle scheme, keyed on q-row)
#pragma unroll
        for (int i = 0; i < 4; i++) {
            int r = r0 + i;
#pragma unroll
            for (int j = 0; j < 4; j++)
                KP[r * 64 + ((tx ^ (r & 15)) * 4 + j)] = p[i][j];
        }
        __syncthreads();

        // O += P @ V
#pragma unroll
        for (int k4 = 0; k4 < 16; k4++) {
            float4 p4[4], v4[4];
#pragma unroll
            for (int i = 0; i < 4; i++) {
                int r = r0 + i;
                p4[i] = *(const float4*)&KP[r * 64 + ((k4 ^ (r & 15)) * 4)];
            }
#pragma unroll
            for (int j = 0; j < 4; j++) {
                int c = c0 + j;
                v4[j] = *(const float4*)&Vt[c * 64 + ((k4 ^ (c & 15)) * 4)];
            }
#pragma unroll
            for (int i = 0; i < 4; i++)
#pragma unroll
                for (int j = 0; j < 4; j++) {
                    o[i][j] = fmaf(p4[i].x, v4[j].x, o[i][j]);
                    o[i][j] = fmaf(p4[i].y, v4[j].y, o[i][j]);
                    o[i][j] = fmaf(p4[i].z, v4[j].z, o[i][j]);
                    o[i][j] = fmaf(p4[i].w, v4[j].w, o[i][j]);
                }
        }
    }

    // Normalize and write to g_Y [B,T,C]
    const int b = bh >> 4, h = bh & 15;
#pragma unroll
    for (int i = 0; i < 4; i++) {
        float inv = 1.f / lr[i];
        size_t row = (size_t)(b * TSEQ + q0 + r0 + i) * CDIM + (size_t)h * HDIM + c0;
#pragma unroll
        for (int j = 0; j < 4; j++)
            g_Y[row + j] = o[i][j] * inv;
    }
}

// ---------------------------------------------------------------------------
// Launch
// ---------------------------------------------------------------------------
extern "C" void kernel_launch(void* const* d_in, const int* in_sizes, int n_in,
                              void* d_out, int out_size)
{
    (void)in_sizes; (void)n_in; (void)out_size;
    const float* x      = (const float*)d_in[0];
    const float* w_attn = (const float*)d_in[1];
    const float* b_attn = (const float*)d_in[2];
    const float* w_proj = (const float*)d_in[3];
    const float* b_proj = (const float*)d_in[4];
    float* out = (float*)d_out;

    float* yptr = nullptr;
    cudaGetSymbolAddress((void**)&yptr, g_Y);

    // 1) QKV projection + scatter into [B,H,T,HD]
    gemm_kernel<3 * CDIM, 0><<<dim3(3 * CDIM / 128, NB * TSEQ / 128), 256>>>(
        x, w_attn, b_attn, nullptr);

    // 2) causal attention -> g_Y [B,T,C]
    attn_kernel<<<dim3(TSEQ / 64, NB * NH), 256>>>();

    // 3) output projection -> d_out
    gemm_kernel<CDIM, 1><<<dim3(CDIM / 128, NB * TSEQ / 128), 256>>>(
        yptr, w_proj, b_proj, out);
}

// round 3
// speedup vs baseline: 1.3096x; 1.3096x over previous
#include <cuda_runtime.h>
#include <cuda_bf16.h>
#include <cstdint>

#define TSEQ 2048
#define NB   2
#define NH   16
#define HDIM 64
#define CDIM 1024
#define MTOT (NB * TSEQ)          // 4096

// ---------------- device-global scratch (allocation-free, graph-safe) -------
__device__ float g_Q[(size_t)NB * NH * TSEQ * HDIM];   // [B,H,T,HD] fp32
__device__ float g_K[(size_t)NB * NH * TSEQ * HDIM];
__device__ float g_V[(size_t)NB * NH * TSEQ * HDIM];

__device__ __nv_bfloat16 g_Xhi[(size_t)MTOT * CDIM];    // x split [4096,1024]
__device__ __nv_bfloat16 g_Xlo[(size_t)MTOT * CDIM];
__device__ __nv_bfloat16 g_Whi[(size_t)3 * CDIM * CDIM]; // w_attn^T [3072,1024]
__device__ __nv_bfloat16 g_Wlo[(size_t)3 * CDIM * CDIM];
__device__ __nv_bfloat16 g_Phi[(size_t)CDIM * CDIM];    // w_proj^T [1024,1024]
__device__ __nv_bfloat16 g_Plo[(size_t)CDIM * CDIM];
__device__ __nv_bfloat16 g_Yhi[(size_t)MTOT * CDIM];    // attn out split
__device__ __nv_bfloat16 g_Ylo[(size_t)MTOT * CDIM];

// ---------------- helpers ---------------------------------------------------
static __device__ __forceinline__ uint32_t smem_u32(const void* p) {
    uint32_t a;
    asm("{ .reg .u64 t; cvta.to.shared.u64 t, %1; cvt.u32.u64 %0, t; }"
        : "=r"(a) : "l"(p));
    return a;
}

#define LDSM4(d0, d1, d2, d3, a)                                              \
    asm volatile("ldmatrix.sync.aligned.m8n8.x4.shared.b16 {%0,%1,%2,%3}, [%4];" \
                 : "=r"(d0), "=r"(d1), "=r"(d2), "=r"(d3) : "r"(a))

#define MMA16816(c0, c1, c2, c3, a0, a1, a2, a3, b0, b1)                      \
    asm volatile(                                                             \
        "mma.sync.aligned.m16n8k16.row.col.f32.bf16.bf16.f32 "                \
        "{%0,%1,%2,%3}, {%4,%5,%6,%7}, {%8,%9}, {%0,%1,%2,%3};"               \
        : "+f"(c0), "+f"(c1), "+f"(c2), "+f"(c3)                              \
        : "r"(a0), "r"(a1), "r"(a2), "r"(a3), "r"(b0), "r"(b1))

#define CP_ASYNC16(smem, gptr)                                                \
    asm volatile("cp.async.cg.shared.global [%0], [%1], 16;"                  \
                 :: "r"(smem), "l"(gptr) : "memory")
#define CP_COMMIT() asm volatile("cp.async.commit_group;" ::: "memory")
#define CP_WAIT1()  asm volatile("cp.async.wait_group 1;" ::: "memory")

// swizzled byte offset within an 8KB tile buffer: 128 rows x 64B (32 bf16)
static __device__ __forceinline__ uint32_t sw_off(int r, int c /*16B chunk*/) {
    return (uint32_t)(r * 64 + ((c ^ ((r >> 1) & 3)) << 4));
}

// ---------------- pre-pass: fp32 -> (hi, lo) bf16 split ---------------------
static __device__ __forceinline__ void split2(float v, __nv_bfloat16& h,
                                              __nv_bfloat16& l) {
    h = __float2bfloat16(v);
    l = __float2bfloat16(v - __bfloat162float(h));
}

__global__ void conv_split(const float* __restrict__ in,
                           __nv_bfloat16* __restrict__ ohi,
                           __nv_bfloat16* __restrict__ olo) {
    int i = blockIdx.x * blockDim.x + threadIdx.x;
    float4 v = ((const float4*)in)[i];
    __nv_bfloat16 h[4], l[4];
    split2(v.x, h[0], l[0]); split2(v.y, h[1], l[1]);
    split2(v.z, h[2], l[2]); split2(v.w, h[3], l[3]);
    uint2 hp, lp;
    hp.x = (uint32_t)__bfloat16_as_ushort(h[0]) | ((uint32_t)__bfloat16_as_ushort(h[1]) << 16);
    hp.y = (uint32_t)__bfloat16_as_ushort(h[2]) | ((uint32_t)__bfloat16_as_ushort(h[3]) << 16);
    lp.x = (uint32_t)__bfloat16_as_ushort(l[0]) | ((uint32_t)__bfloat16_as_ushort(l[1]) << 16);
    lp.y = (uint32_t)__bfloat16_as_ushort(l[2]) | ((uint32_t)__bfloat16_as_ushort(l[3]) << 16);
    ((uint2*)ohi)[i] = hp;
    ((uint2*)olo)[i] = lp;
}

// transpose [R,C] fp32 -> [C,R] split bf16
__global__ void trans_split(const float* __restrict__ in,
                            __nv_bfloat16* __restrict__ ohi,
                            __nv_bfloat16* __restrict__ olo, int R, int C) {
    __shared__ float t[32][33];
    int x = blockIdx.x * 32 + threadIdx.x;
    int y = blockIdx.y * 32 + threadIdx.y;
#pragma unroll
    for (int j = 0; j < 32; j += 8)
        t[threadIdx.y + j][threadIdx.x] = in[(size_t)(y + j) * C + x];
    __syncthreads();
    int ox = blockIdx.y * 32 + threadIdx.x;
    int oy = blockIdx.x * 32 + threadIdx.y;
#pragma unroll
    for (int j = 0; j < 32; j += 8) {
        float v = t[threadIdx.x][threadIdx.y + j];
        __nv_bfloat16 h, l; split2(v, h, l);
        ohi[(size_t)(oy + j) * R + ox] = h;
        olo[(size_t)(oy + j) * R + ox] = l;
    }
}

// ---------------- warp-MMA split-bf16 GEMM ----------------------------------
// D[4096, N] = (Ahi+Alo)[4096,1024] @ (Bhi+Blo)[N,1024]^T + bias
// Block tile 128x128, BK=32, 8 warps (warp tile 64x32), cp.async double buffer.
// Smem per stage: Ahi|Alo|Bhi|Blo, each 128 rows x 64B (8KB) = 32KB. 2 stages.
static constexpr int SMEM_DYN = 2 * 32768;
static constexpr int NKI = CDIM / 32;   // 32 k-iterations

template <int N, int MODE>
__launch_bounds__(256)
__global__ void mma_gemm(const __nv_bfloat16* __restrict__ Ahi,
                         const __nv_bfloat16* __restrict__ Alo,
                         const __nv_bfloat16* __restrict__ Bhi,
                         const __nv_bfloat16* __restrict__ Blo,
                         const float* __restrict__ bias,
                         float* __restrict__ out) {
    extern __shared__ __align__(128) char dsm[];
    const uint32_t sbase = smem_u32(dsm);

    const int tid = threadIdx.x;
    const int wid = tid >> 5, lane = tid & 31;
    const int warp_m = (wid >> 2) * 64;    // 0 or 64
    const int warp_n = (wid & 3) * 32;     // 0,32,64,96
    const int m0 = blockIdx.y * 128, n0 = blockIdx.x * 128;

    // per-thread cp.async assignment: 8 chunks of 16B
    int ld_buf[8], ld_row[8], ld_ch[8];
    const __nv_bfloat16* gsrc[8];
#pragma unroll
    for (int i = 0; i < 8; ++i) {
        int idx = tid + i * 256;           // 0..2047
        int buf = idx >> 9;                // 0..3
        int id2 = idx & 511;
        int r = id2 >> 2, c = id2 & 3;
        ld_buf[i] = buf; ld_row[i] = r; ld_ch[i] = c;
        const __nv_bfloat16* base =
            (buf == 0) ? Ahi : (buf == 1) ? Alo : (buf == 2) ? Bhi : Blo;
        int grow = (buf < 2) ? (m0 + r) : (n0 + r);
        gsrc[i] = base + (size_t)grow * CDIM + c * 8;
    }

    auto issue_stage = [&](int it, int stage) {
        uint32_t st = sbase + stage * 32768;
#pragma unroll
        for (int i = 0; i < 8; ++i) {
            uint32_t dst = st + ld_buf[i] * 8192 + sw_off(ld_row[i], ld_ch[i]);
            CP_ASYNC16(dst, gsrc[i] + it * 32);
        }
    };

    // ldmatrix per-lane row bases
    const int lrow = lane & 15;
    const int lhalf = lane >> 4;           // 16B chunk half within k16
    int rA[4], rB[2];
#pragma unroll
    for (int mt = 0; mt < 4; ++mt) rA[mt] = warp_m + mt * 16 + lrow;
#pragma unroll
    for (int bp = 0; bp < 2; ++bp) rB[bp] = warp_n + bp * 16 + lrow;

    float acc[4][4][4];
#pragma unroll
    for (int mt = 0; mt < 4; ++mt)
#pragma unroll
        for (int nt = 0; nt < 4; ++nt)
#pragma unroll
            for (int e = 0; e < 4; ++e) acc[mt][nt][e] = 0.f;

    issue_stage(0, 0);
    CP_COMMIT();

    for (int it = 0; it < NKI; ++it) {
        if (it + 1 < NKI) issue_stage(it + 1, (it + 1) & 1);
        CP_COMMIT();
        CP_WAIT1();
        __syncthreads();

        uint32_t st = sbase + (it & 1) * 32768;
#pragma unroll
        for (int ks = 0; ks < 2; ++ks) {
            const int ch = 2 * ks + lhalf;
            uint32_t ah[4][4], al[4][4], bh[2][4], bl[2][4];
#pragma unroll
            for (int mt = 0; mt < 4; ++mt) {
                uint32_t a = st + sw_off(rA[mt], ch);
                LDSM4(ah[mt][0], ah[mt][1], ah[mt][2], ah[mt][3], a);
                LDSM4(al[mt][0], al[mt][1], al[mt][2], al[mt][3], a + 8192);
            }
#pragma unroll
            for (int bp = 0; bp < 2; ++bp) {
                uint32_t b = st + 16384 + sw_off(rB[bp], ch);
                LDSM4(bh[bp][0], bh[bp][1], bh[bp][2], bh[bp][3], b);
                LDSM4(bl[bp][0], bl[bp][1], bl[bp][2], bl[bp][3], b + 8192);
            }
#pragma unroll
            for (int mt = 0; mt < 4; ++mt)
#pragma unroll
                for (int bp = 0; bp < 2; ++bp)
#pragma unroll
                    for (int sub = 0; sub < 2; ++sub) {
                        int nt = bp * 2 + sub;
                        float* c = acc[mt][nt];
                        MMA16816(c[0], c[1], c[2], c[3],
                                 ah[mt][0], ah[mt][1], ah[mt][2], ah[mt][3],
                                 bh[bp][sub], bh[bp][sub + 2]);
                        MMA16816(c[0], c[1], c[2], c[3],
                                 ah[mt][0], ah[mt][1], ah[mt][2], ah[mt][3],
                                 bl[bp][sub], bl[bp][sub + 2]);
                        MMA16816(c[0], c[1], c[2], c[3],
                                 al[mt][0], al[mt][1], al[mt][2], al[mt][3],
                                 bh[bp][sub], bh[bp][sub + 2]);
                    }
        }
        __syncthreads();
    }

    // epilogue: fragment layout c0,c1 -> (row g, n+0/1), c2,c3 -> (row g+8)
    const int g = lane >> 2, tig = lane & 3;
#pragma unroll
    for (int mt = 0; mt < 4; ++mt) {
#pragma unroll
        for (int nt = 0; nt < 4; ++nt) {
            int n = n0 + warp_n + nt * 8 + tig * 2;
            int mlo = m0 + warp_m + mt * 16 + g;
            int mhi = mlo + 8;
            float2 bv = *(const float2*)&bias[n];
            float2 v0 = make_float2(acc[mt][nt][0] + bv.x, acc[mt][nt][1] + bv.y);
            float2 v1 = make_float2(acc[mt][nt][2] + bv.x, acc[mt][nt][3] + bv.y);
            if (MODE == 0) {
                int seg = n >> 10;
                int c = n & 1023;
                int h = c >> 6, d = c & 63;
                float* dst = (seg == 0) ? g_Q : (seg == 1) ? g_K : g_V;
                {
                    int b = mlo >> 11, t = mlo & 2047;
                    *(float2*)&dst[(((size_t)b * NH + h) * TSEQ + t) * HDIM + d] = v0;
                }
                {
                    int b = mhi >> 11, t = mhi & 2047;
                    *(float2*)&dst[(((size_t)b * NH + h) * TSEQ + t) * HDIM + d] = v1;
                }
            } else {
                *(float2*)&out[(size_t)mlo * N + n] = v0;
                *(float2*)&out[(size_t)mhi * N + n] = v1;
            }
        }
    }
}

// ---------------- flash-style causal attention (fp32 SIMT) ------------------
__launch_bounds__(256)
__global__ void attn_kernel() {
    __shared__ float Qs[64 * 64];
    __shared__ float KP[64 * 64];
    __shared__ float Vt[64 * 64];

    const int tid = threadIdx.x;
    const int ty = tid >> 4, tx = tid & 15;
    const int bh = blockIdx.y;
    const int q0 = blockIdx.x * 64;
    const float* Qg = g_Q + (size_t)bh * TSEQ * HDIM;
    const float* Kg = g_K + (size_t)bh * TSEQ * HDIM;
    const float* Vg = g_V + (size_t)bh * TSEQ * HDIM;

#pragma unroll
    for (int u = 0; u < 4; u++) {
        int idx = tid + u * 256;
        int r = idx >> 4, c4 = idx & 15;
        float4 q = *(const float4*)&Qg[(size_t)(q0 + r) * HDIM + c4 * 4];
        q.x *= 0.125f; q.y *= 0.125f; q.z *= 0.125f; q.w *= 0.125f;
        *(float4*)&Qs[r * 64 + c4 * 4] = q;
    }

    float o[4][4];
    float mr[4], lr[4];
#pragma unroll
    for (int i = 0; i < 4; i++) {
        mr[i] = -1e30f; lr[i] = 0.f;
#pragma unroll
        for (int j = 0; j < 4; j++) o[i][j] = 0.f;
    }

    const int r0 = ty * 4;
    const int c0 = tx * 4;
    const int nkt = blockIdx.x + 1;

    for (int kt = 0; kt < nkt; kt++) {
        const int k0 = kt * 64;
        __syncthreads();
#pragma unroll
        for (int u = 0; u < 4; u++) {
            int idx = tid + u * 256;
            int r = idx >> 4, c4 = idx & 15;
            float4 kv = *(const float4*)&Kg[(size_t)(k0 + r) * HDIM + c4 * 4];
            *(float4*)&KP[r * 64 + ((c4 ^ (r & 15)) * 4)] = kv;
            float4 vv = *(const float4*)&Vg[(size_t)(k0 + r) * HDIM + c4 * 4];
            int k4 = r >> 2, kin = r & 3;
            { int d = c4 * 4 + 0; Vt[d * 64 + ((k4 ^ (d & 15)) * 4 + kin)] = vv.x; }
            { int d = c4 * 4 + 1; Vt[d * 64 + ((k4 ^ (d & 15)) * 4 + kin)] = vv.y; }
            { int d = c4 * 4 + 2; Vt[d * 64 + ((k4 ^ (d & 15)) * 4 + kin)] = vv.z; }
            { int d = c4 * 4 + 3; Vt[d * 64 + ((k4 ^ (d & 15)) * 4 + kin)] = vv.w; }
        }
        __syncthreads();

        float s[4][4];
#pragma unroll
        for (int i = 0; i < 4; i++)
#pragma unroll
            for (int j = 0; j < 4; j++) s[i][j] = 0.f;
#pragma unroll
        for (int d4 = 0; d4 < 16; d4++) {
            float4 q4[4], k4v[4];
#pragma unroll
            for (int i = 0; i < 4; i++)
                q4[i] = *(const float4*)&Qs[(r0 + i) * 64 + d4 * 4];
#pragma unroll
            for (int j = 0; j < 4; j++) {
                int c = c0 + j;
                k4v[j] = *(const float4*)&KP[c * 64 + ((d4 ^ (c & 15)) * 4)];
            }
#pragma unroll
            for (int i = 0; i < 4; i++)
#pragma unroll
                for (int j = 0; j < 4; j++) {
                    s[i][j] = fmaf(q4[i].x, k4v[j].x, s[i][j]);
                    s[i][j] = fmaf(q4[i].y, k4v[j].y, s[i][j]);
                    s[i][j] = fmaf(q4[i].z, k4v[j].z, s[i][j]);
                    s[i][j] = fmaf(q4[i].w, k4v[j].w, s[i][j]);
                }
        }

        if (kt == nkt - 1) {
#pragma unroll
            for (int i = 0; i < 4; i++)
#pragma unroll
                for (int j = 0; j < 4; j++)
                    if (k0 + c0 + j > q0 + r0 + i) s[i][j] = -1e30f;
        }

        float p[4][4];
#pragma unroll
        for (int i = 0; i < 4; i++) {
            float rm = fmaxf(fmaxf(s[i][0], s[i][1]), fmaxf(s[i][2], s[i][3]));
            rm = fmaxf(rm, __shfl_xor_sync(0xffffffffu, rm, 8));
            rm = fmaxf(rm, __shfl_xor_sync(0xffffffffu, rm, 4));
            rm = fmaxf(rm, __shfl_xor_sync(0xffffffffu, rm, 2));
            rm = fmaxf(rm, __shfl_xor_sync(0xffffffffu, rm, 1));
            float mn = fmaxf(mr[i], rm);
            float alpha = __expf(mr[i] - mn);
            mr[i] = mn;
            float rs = 0.f;
#pragma unroll
            for (int j = 0; j < 4; j++) {
                p[i][j] = __expf(s[i][j] - mn);
                rs += p[i][j];
            }
            rs += __shfl_xor_sync(0xffffffffu, rs, 8);
            rs += __shfl_xor_sync(0xffffffffu, rs, 4);
            rs += __shfl_xor_sync(0xffffffffu, rs, 2);
            rs += __shfl_xor_sync(0xffffffffu, rs, 1);
            lr[i] = lr[i] * alpha + rs;
#pragma unroll
            for (int j = 0; j < 4; j++) o[i][j] *= alpha;
        }

        __syncthreads();
#pragma unroll
        for (int i = 0; i < 4; i++) {
            int r = r0 + i;
#pragma unroll
            for (int j = 0; j < 4; j++)
                KP[r * 64 + ((tx ^ (r & 15)) * 4 + j)] = p[i][j];
        }
        __syncthreads();

#pragma unroll
        for (int k4 = 0; k4 < 16; k4++) {
            float4 p4[4], v4[4];
#pragma unroll
            for (int i = 0; i < 4; i++) {
                int r = r0 + i;
                p4[i] = *(const float4*)&KP[r * 64 + ((k4 ^ (r & 15)) * 4)];
            }
#pragma unroll
            for (int j = 0; j < 4; j++) {
                int c = c0 + j;
                v4[j] = *(const float4*)&Vt[c * 64 + ((k4 ^ (c & 15)) * 4)];
            }
#pragma unroll
            for (int i = 0; i < 4; i++)
#pragma unroll
                for (int j = 0; j < 4; j++) {
                    o[i][j] = fmaf(p4[i].x, v4[j].x, o[i][j]);
                    o[i][j] = fmaf(p4[i].y, v4[j].y, o[i][j]);
                    o[i][j] = fmaf(p4[i].z, v4[j].z, o[i][j]);
                    o[i][j] = fmaf(p4[i].w, v4[j].w, o[i][j]);
                }
        }
    }

    // write split bf16 (feeds the proj GEMM)
    const int b = bh >> 4, h = bh & 15;
#pragma unroll
    for (int i = 0; i < 4; i++) {
        float inv = 1.f / lr[i];
        size_t row = (size_t)(b * TSEQ + q0 + r0 + i) * CDIM + (size_t)h * HDIM + c0;
#pragma unroll
        for (int j = 0; j < 4; j++) {
            float v = o[i][j] * inv;
            __nv_bfloat16 hh, ll; split2(v, hh, ll);
            g_Yhi[row + j] = hh;
            g_Ylo[row + j] = ll;
        }
    }
}

// ---------------- launch ----------------------------------------------------
extern "C" void kernel_launch(void* const* d_in, const int* in_sizes, int n_in,
                              void* d_out, int out_size) {
    (void)in_sizes; (void)n_in; (void)out_size;
    const float* x      = (const float*)d_in[0];
    const float* w_attn = (const float*)d_in[1];
    const float* b_attn = (const float*)d_in[2];
    const float* w_proj = (const float*)d_in[3];
    const float* b_proj = (const float*)d_in[4];
    float* out = (float*)d_out;

    cudaFuncSetAttribute(mma_gemm<3 * CDIM, 0>,
                         cudaFuncAttributeMaxDynamicSharedMemorySize, SMEM_DYN);
    cudaFuncSetAttribute(mma_gemm<CDIM, 1>,
                         cudaFuncAttributeMaxDynamicSharedMemorySize, SMEM_DYN);

    __nv_bfloat16 *xhi, *xlo, *whi, *wlo, *phi, *plo, *yhi, *ylo;
    cudaGetSymbolAddress((void**)&xhi, g_Xhi);
    cudaGetSymbolAddress((void**)&xlo, g_Xlo);
    cudaGetSymbolAddress((void**)&whi, g_Whi);
    cudaGetSymbolAddress((void**)&wlo, g_Wlo);
    cudaGetSymbolAddress((void**)&phi, g_Phi);
    cudaGetSymbolAddress((void**)&plo, g_Plo);
    cudaGetSymbolAddress((void**)&yhi, g_Yhi);
    cudaGetSymbolAddress((void**)&ylo, g_Ylo);

    // pre-pass: split x, transpose+split weights
    conv_split<<<(MTOT * CDIM / 4) / 256, 256>>>(x, xhi, xlo);
    trans_split<<<dim3(3 * CDIM / 32, CDIM / 32), dim3(32, 8)>>>(
        w_attn, whi, wlo, CDIM, 3 * CDIM);
    trans_split<<<dim3(CDIM / 32, CDIM / 32), dim3(32, 8)>>>(
        w_proj, phi, plo, CDIM, CDIM);

    // 1) QKV projection (warp MMA) -> scatter into [B,H,T,HD]
    mma_gemm<3 * CDIM, 0><<<dim3(3 * CDIM / 128, MTOT / 128), 256, SMEM_DYN>>>(
        xhi, xlo, whi, wlo, b_attn, nullptr);

    // 2) causal attention -> g_Yhi/g_Ylo
    attn_kernel<<<dim3(TSEQ / 64, NB * NH), 256>>>();

    // 3) output projection (warp MMA) -> d_out
    mma_gemm<CDIM, 1><<<dim3(CDIM / 128, MTOT / 128), 256, SMEM_DYN>>>(
        yhi, ylo, phi, plo, b_proj, out);
}

// round 4
// speedup vs baseline: 3.8206x; 2.9174x over previous
#include <cuda_runtime.h>
#include <cuda_bf16.h>
#include <cstdint>

#define TSEQ 2048
#define NB   2
#define NH   16
#define HDIM 64
#define CDIM 1024
#define MTOT (NB * TSEQ)          // 4096
#define BHT  (NB * NH)            // 32

// ---------------- device-global scratch (allocation-free, graph-safe) -------
__device__ __nv_bfloat16 g_Qh[(size_t)BHT * TSEQ * HDIM];  // [bh][t][hd], pre-scaled 0.125
__device__ __nv_bfloat16 g_Ql[(size_t)BHT * TSEQ * HDIM];
__device__ __nv_bfloat16 g_Kh[(size_t)BHT * TSEQ * HDIM];  // [bh][t][hd]
__device__ __nv_bfloat16 g_Kl[(size_t)BHT * TSEQ * HDIM];
__device__ __nv_bfloat16 g_Vh[(size_t)BHT * HDIM * TSEQ];  // [bh][hd][t]  (transposed)
__device__ __nv_bfloat16 g_Vl[(size_t)BHT * HDIM * TSEQ];

__device__ __nv_bfloat16 g_Xhi[(size_t)MTOT * CDIM];    // x split [4096,1024]
__device__ __nv_bfloat16 g_Xlo[(size_t)MTOT * CDIM];
__device__ __nv_bfloat16 g_Whi[(size_t)3 * CDIM * CDIM]; // w_attn^T [3072,1024]
__device__ __nv_bfloat16 g_Wlo[(size_t)3 * CDIM * CDIM];
__device__ __nv_bfloat16 g_Phi[(size_t)CDIM * CDIM];    // w_proj^T [1024,1024]
__device__ __nv_bfloat16 g_Plo[(size_t)CDIM * CDIM];
__device__ __nv_bfloat16 g_Yhi[(size_t)MTOT * CDIM];    // attn out split [t][C]
__device__ __nv_bfloat16 g_Ylo[(size_t)MTOT * CDIM];

// ---------------- helpers ---------------------------------------------------
static __device__ __forceinline__ uint32_t smem_u32(const void* p) {
    uint32_t a;
    asm("{ .reg .u64 t; cvta.to.shared.u64 t, %1; cvt.u32.u64 %0, t; }"
        : "=r"(a) : "l"(p));
    return a;
}

#define LDSM4(d0, d1, d2, d3, a)                                              \
    asm volatile("ldmatrix.sync.aligned.m8n8.x4.shared.b16 {%0,%1,%2,%3}, [%4];" \
                 : "=r"(d0), "=r"(d1), "=r"(d2), "=r"(d3) : "r"(a))

#define MMA16816(c0, c1, c2, c3, a0, a1, a2, a3, b0, b1)                      \
    asm volatile(                                                             \
        "mma.sync.aligned.m16n8k16.row.col.f32.bf16.bf16.f32 "                \
        "{%0,%1,%2,%3}, {%4,%5,%6,%7}, {%8,%9}, {%0,%1,%2,%3};"               \
        : "+f"(c0), "+f"(c1), "+f"(c2), "+f"(c3)                              \
        : "r"(a0), "r"(a1), "r"(a2), "r"(a3), "r"(b0), "r"(b1))

#define CP_ASYNC16(smem, gptr)                                                \
    asm volatile("cp.async.cg.shared.global [%0], [%1], 16;"                  \
                 :: "r"(smem), "l"(gptr) : "memory")
#define CP_COMMIT() asm volatile("cp.async.commit_group;" ::: "memory")
#define CP_WAIT1()  asm volatile("cp.async.wait_group 1;" ::: "memory")

// r = {lo: bf16(flo), hi: bf16(fhi)}
#define PACK_BF2(r, flo, fhi)                                                 \
    asm volatile("cvt.rn.bf16x2.f32 %0, %1, %2;" : "=r"(r) : "f"(fhi), "f"(flo))

// swizzled byte offset in a tile buffer of 64B rows (32 bf16), c = 16B chunk 0..3
static __device__ __forceinline__ uint32_t sw_off(int r, int c) {
    return (uint32_t)(r * 64 + ((c ^ ((r >> 1) & 3)) << 4));
}

static __device__ __forceinline__ void split2(float v, __nv_bfloat16& h,
                                              __nv_bfloat16& l) {
    h = __float2bfloat16(v);
    l = __float2bfloat16(v - __bfloat162float(h));
}
static __device__ __forceinline__ uint32_t pack_bf(__nv_bfloat16 a, __nv_bfloat16 b) {
    return (uint32_t)__bfloat16_as_ushort(a) | ((uint32_t)__bfloat16_as_ushort(b) << 16);
}

// ---------------- pre-pass kernels ------------------------------------------
__global__ void conv_split(const float* __restrict__ in,
                           __nv_bfloat16* __restrict__ ohi,
                           __nv_bfloat16* __restrict__ olo) {
    int i = blockIdx.x * blockDim.x + threadIdx.x;
    float4 v = ((const float4*)in)[i];
    __nv_bfloat16 h[4], l[4];
    split2(v.x, h[0], l[0]); split2(v.y, h[1], l[1]);
    split2(v.z, h[2], l[2]); split2(v.w, h[3], l[3]);
    uint2 hp, lp;
    hp.x = pack_bf(h[0], h[1]); hp.y = pack_bf(h[2], h[3]);
    lp.x = pack_bf(l[0], l[1]); lp.y = pack_bf(l[2], l[3]);
    ((uint2*)ohi)[i] = hp;
    ((uint2*)olo)[i] = lp;
}

__global__ void trans_split(const float* __restrict__ in,
                            __nv_bfloat16* __restrict__ ohi,
                            __nv_bfloat16* __restrict__ olo, int R, int C) {
    __shared__ float t[32][33];
    int x = blockIdx.x * 32 + threadIdx.x;
    int y = blockIdx.y * 32 + threadIdx.y;
#pragma unroll
    for (int j = 0; j < 32; j += 8)
        t[threadIdx.y + j][threadIdx.x] = in[(size_t)(y + j) * C + x];
    __syncthreads();
    int ox = blockIdx.y * 32 + threadIdx.x;
    int oy = blockIdx.x * 32 + threadIdx.y;
#pragma unroll
    for (int j = 0; j < 32; j += 8) {
        float v = t[threadIdx.x][threadIdx.y + j];
        __nv_bfloat16 h, l; split2(v, h, l);
        ohi[(size_t)(oy + j) * R + ox] = h;
        olo[(size_t)(oy + j) * R + ox] = l;
    }
}

// ---------------- warp-MMA split-bf16 GEMM ----------------------------------
static constexpr int SMEM_DYN = 2 * 32768;
static constexpr int NKI = CDIM / 32;

template <int N, int MODE>
__launch_bounds__(256)
__global__ void mma_gemm(const __nv_bfloat16* __restrict__ Ahi,
                         const __nv_bfloat16* __restrict__ Alo,
                         const __nv_bfloat16* __restrict__ Bhi,
                         const __nv_bfloat16* __restrict__ Blo,
                         const float* __restrict__ bias,
                         float* __restrict__ out) {
    extern __shared__ __align__(128) char dsm[];
    const uint32_t sbase = smem_u32(dsm);

    const int tid = threadIdx.x;
    const int wid = tid >> 5, lane = tid & 31;
    const int warp_m = (wid >> 2) * 64;
    const int warp_n = (wid & 3) * 32;
    const int m0 = blockIdx.y * 128, n0 = blockIdx.x * 128;

    int ld_buf[8], ld_row[8], ld_ch[8];
    const __nv_bfloat16* gsrc[8];
#pragma unroll
    for (int i = 0; i < 8; ++i) {
        int idx = tid + i * 256;
        int buf = idx >> 9;
        int id2 = idx & 511;
        int r = id2 >> 2, c = id2 & 3;
        ld_buf[i] = buf; ld_row[i] = r; ld_ch[i] = c;
        const __nv_bfloat16* base =
            (buf == 0) ? Ahi : (buf == 1) ? Alo : (buf == 2) ? Bhi : Blo;
        int grow = (buf < 2) ? (m0 + r) : (n0 + r);
        gsrc[i] = base + (size_t)grow * CDIM + c * 8;
    }

    auto issue_stage = [&](int it, int stage) {
        uint32_t st = sbase + stage * 32768;
#pragma unroll
        for (int i = 0; i < 8; ++i) {
            uint32_t dst = st + ld_buf[i] * 8192 + sw_off(ld_row[i] * 1, ld_ch[i]);
            CP_ASYNC16(dst, gsrc[i] + it * 32);
        }
    };

    const int lrow = lane & 15;
    const int lhalf = lane >> 4;
    int rA[4], rB[2];
#pragma unroll
    for (int mt = 0; mt < 4; ++mt) rA[mt] = warp_m + mt * 16 + lrow;
#pragma unroll
    for (int bp = 0; bp < 2; ++bp) rB[bp] = warp_n + bp * 16 + lrow;

    float acc[4][4][4];
#pragma unroll
    for (int mt = 0; mt < 4; ++mt)
#pragma unroll
        for (int nt = 0; nt < 4; ++nt)
#pragma unroll
            for (int e = 0; e < 4; ++e) acc[mt][nt][e] = 0.f;

    issue_stage(0, 0);
    CP_COMMIT();

    for (int it = 0; it < NKI; ++it) {
        if (it + 1 < NKI) issue_stage(it + 1, (it + 1) & 1);
        CP_COMMIT();
        CP_WAIT1();
        __syncthreads();

        uint32_t st = sbase + (it & 1) * 32768;
#pragma unroll
        for (int ks = 0; ks < 2; ++ks) {
            const int ch = 2 * ks + lhalf;
            uint32_t ah[4][4], al[4][4], bh[2][4], bl[2][4];
#pragma unroll
            for (int mt = 0; mt < 4; ++mt) {
                uint32_t a = st + sw_off(rA[mt], ch);
                LDSM4(ah[mt][0], ah[mt][1], ah[mt][2], ah[mt][3], a);
                LDSM4(al[mt][0], al[mt][1], al[mt][2], al[mt][3], a + 8192);
            }
#pragma unroll
            for (int bp = 0; bp < 2; ++bp) {
                uint32_t b = st + 16384 + sw_off(rB[bp], ch);
                LDSM4(bh[bp][0], bh[bp][1], bh[bp][2], bh[bp][3], b);
                LDSM4(bl[bp][0], bl[bp][1], bl[bp][2], bl[bp][3], b + 8192);
            }
#pragma unroll
            for (int mt = 0; mt < 4; ++mt)
#pragma unroll
                for (int bp = 0; bp < 2; ++bp)
#pragma unroll
                    for (int sub = 0; sub < 2; ++sub) {
                        int nt = bp * 2 + sub;
                        float* c = acc[mt][nt];
                        MMA16816(c[0], c[1], c[2], c[3],
                                 ah[mt][0], ah[mt][1], ah[mt][2], ah[mt][3],
                                 bh[bp][sub], bh[bp][sub + 2]);
                        MMA16816(c[0], c[1], c[2], c[3],
                                 ah[mt][0], ah[mt][1], ah[mt][2], ah[mt][3],
                                 bl[bp][sub], bl[bp][sub + 2]);
                        MMA16816(c[0], c[1], c[2], c[3],
                                 al[mt][0], al[mt][1], al[mt][2], al[mt][3],
                                 bh[bp][sub], bh[bp][sub + 2]);
                    }
        }
        __syncthreads();
    }

    const int g = lane >> 2, tig = lane & 3;
#pragma unroll
    for (int mt = 0; mt < 4; ++mt) {
#pragma unroll
        for (int nt = 0; nt < 4; ++nt) {
            int n = n0 + warp_n + nt * 8 + tig * 2;
            int mlo = m0 + warp_m + mt * 16 + g;
            float2 bv = *(const float2*)&bias[n];
            float2 vv[2];
            vv[0] = make_float2(acc[mt][nt][0] + bv.x, acc[mt][nt][1] + bv.y);
            vv[1] = make_float2(acc[mt][nt][2] + bv.x, acc[mt][nt][3] + bv.y);
            if (MODE == 0) {
                int seg = n >> 10;
                int c = n & 1023;
                int h = c >> 6, d = c & 63;
#pragma unroll
                for (int p = 0; p < 2; ++p) {
                    int m = mlo + p * 8;
                    int b = m >> 11, t = m & 2047;
                    int bh = b * NH + h;
                    float vx = vv[p].x, vy = vv[p].y;
                    if (seg == 0) { vx *= 0.125f; vy *= 0.125f; }
                    __nv_bfloat16 hx, lx, hy, ly;
                    split2(vx, hx, lx); split2(vy, hy, ly);
                    if (seg == 2) {
                        size_t o = ((size_t)bh * HDIM + d) * TSEQ + t;
                        g_Vh[o] = hx; g_Vh[o + TSEQ] = hy;
                        g_Vl[o] = lx; g_Vl[o + TSEQ] = ly;
                    } else {
                        size_t o = ((size_t)bh * TSEQ + t) * HDIM + d;
                        __nv_bfloat16* dh = (seg == 0) ? g_Qh : g_Kh;
                        __nv_bfloat16* dl = (seg == 0) ? g_Ql : g_Kl;
                        *(uint32_t*)&dh[o] = pack_bf(hx, hy);
                        *(uint32_t*)&dl[o] = pack_bf(lx, ly);
                    }
                }
            } else {
                *(float2*)&out[(size_t)mlo * N + n] = vv[0];
                *(float2*)&out[(size_t)(mlo + 8) * N + n] = vv[1];
            }
        }
    }
}

// ---------------- tensor-core flash attention --------------------------------
// Block: 128 q-rows of one (b,h). 8 warps x 16 rows. K/V tiles of 64 keys,
// cp.async double-buffered. All matmuls split-bf16 (3 HMMA each).
// Smem: Q (hi+lo) 32KB + 2 stages x (K hi/lo + V^T hi/lo) 32KB = 96KB.
static constexpr int ATT_SMEM = 32768 + 2 * 32768;

__launch_bounds__(256)
__global__ void attn_mma() {
    extern __shared__ __align__(128) char sm[];
    const uint32_t sb = smem_u32(sm);

    const int tid = threadIdx.x, wid = tid >> 5, lane = tid & 31;
    const int lrow = lane & 15, lhalf = lane >> 4;
    const int g = lane >> 2, qd = lane & 3;
    const int qi = blockIdx.x, bh = blockIdx.y;
    const int q0 = qi * 128;
    const int r0w = wid * 16;
    const int nkt = 2 * qi + 2;

    // --- Q tile load (hi+lo), 128x64 each ---
#pragma unroll
    for (int i = 0; i < 8; ++i) {
        int idx = tid + i * 256;              // 0..2047
        int buf = idx >> 10;                  // 0=hi,1=lo
        int rem = idx & 1023;
        int r = rem >> 3, c8 = rem & 7;
        int cb = c8 >> 2, cc = c8 & 3;
        uint32_t dst = sb + buf * 16384 + cb * 8192 + sw_off(r, cc);
        const __nv_bfloat16* src =
            (buf ? g_Ql : g_Qh) + ((size_t)bh * TSEQ + q0 + r) * HDIM + cb * 32 + cc * 8;
        CP_ASYNC16(dst, src);
    }

    auto issue_kv = [&](int kt, int stage) {
        uint32_t st = sb + 32768 + stage * 32768;
#pragma unroll
        for (int i = 0; i < 8; ++i) {
            int idx = tid + i * 256;          // 0..2047
            int buf = idx >> 9;               // 0:KH 1:KL 2:VH 3:VL
            int rem = idx & 511;
            int r = rem >> 3, c8 = rem & 7;
            int cb = c8 >> 2, cc = c8 & 3;
            uint32_t dst = st + buf * 8192 + cb * 4096 + sw_off(r, cc);
            const __nv_bfloat16* src;
            if (buf < 2)
                src = (buf ? g_Kl : g_Kh) +
                      ((size_t)bh * TSEQ + kt * 64 + r) * HDIM + cb * 32 + cc * 8;
            else
                src = ((buf == 3) ? g_Vl : g_Vh) +
                      ((size_t)bh * HDIM + r) * TSEQ + kt * 64 + cb * 32 + cc * 8;
            CP_ASYNC16(dst, src);
        }
    };

    issue_kv(0, 0);
    CP_COMMIT();
    issue_kv(1, 1);
    CP_COMMIT();
    CP_WAIT1();
    __syncthreads();

    float o[8][4];
#pragma unroll
    for (int j = 0; j < 8; ++j)
#pragma unroll
        for (int e = 0; e < 4; ++e) o[j][e] = 0.f;
    float mrun0 = -1e30f, mrun1 = -1e30f;
    float lrun0 = 0.f, lrun1 = 0.f;

    for (int kt = 0; kt < nkt; ++kt) {
        const uint32_t st = sb + 32768 + (kt & 1) * 32768;
        const bool active = (kt * 64 <= q0 + r0w + 15);

        if (active) {
            // ---- S = Q K^T (split: 3 HMMA) ----
            float s[8][4];
#pragma unroll
            for (int j = 0; j < 8; ++j)
#pragma unroll
                for (int e = 0; e < 4; ++e) s[j][e] = 0.f;
#pragma unroll
            for (int ks = 0; ks < 4; ++ks) {
                const int cb = ks >> 1;
                const int c = (ks & 1) * 2 + lhalf;
                uint32_t qh[4], ql[4];
                uint32_t qa = sb + cb * 8192 + sw_off(r0w + lrow, c);
                LDSM4(qh[0], qh[1], qh[2], qh[3], qa);
                LDSM4(ql[0], ql[1], ql[2], ql[3], qa + 16384);
#pragma unroll
                for (int bp = 0; bp < 4; ++bp) {
                    uint32_t kh[4], kl[4];
                    uint32_t ka = st + cb * 4096 + sw_off(bp * 16 + lrow, c);
                    LDSM4(kh[0], kh[1], kh[2], kh[3], ka);
                    LDSM4(kl[0], kl[1], kl[2], kl[3], ka + 8192);
#pragma unroll
                    for (int sub = 0; sub < 2; ++sub) {
                        float* cc2 = s[bp * 2 + sub];
                        MMA16816(cc2[0], cc2[1], cc2[2], cc2[3],
                                 qh[0], qh[1], qh[2], qh[3], kh[sub], kh[sub + 2]);
                        MMA16816(cc2[0], cc2[1], cc2[2], cc2[3],
                                 qh[0], qh[1], qh[2], qh[3], kl[sub], kl[sub + 2]);
                        MMA16816(cc2[0], cc2[1], cc2[2], cc2[3],
                                 ql[0], ql[1], ql[2], ql[3], kh[sub], kh[sub + 2]);
                    }
                }
            }

            // ---- causal mask (only near diagonal) ----
            if (kt * 64 + 63 > q0) {
                const int row0 = q0 + r0w + g, row1 = row0 + 8;
#pragma unroll
                for (int j = 0; j < 8; ++j) {
                    int col = kt * 64 + j * 8 + qd * 2;
                    if (col > row0)     s[j][0] = -1e30f;
                    if (col + 1 > row0) s[j][1] = -1e30f;
                    if (col > row1)     s[j][2] = -1e30f;
                    if (col + 1 > row1) s[j][3] = -1e30f;
                }
            }

            // ---- online softmax + pack P (hi/lo) ----
            float nm0 = -1e30f, nm1 = -1e30f;
#pragma unroll
            for (int j = 0; j < 8; ++j) {
                nm0 = fmaxf(nm0, fmaxf(s[j][0], s[j][1]));
                nm1 = fmaxf(nm1, fmaxf(s[j][2], s[j][3]));
            }
            nm0 = fmaxf(nm0, __shfl_xor_sync(0xffffffffu, nm0, 1));
            nm0 = fmaxf(nm0, __shfl_xor_sync(0xffffffffu, nm0, 2));
            nm1 = fmaxf(nm1, __shfl_xor_sync(0xffffffffu, nm1, 1));
            nm1 = fmaxf(nm1, __shfl_xor_sync(0xffffffffu, nm1, 2));
            nm0 = fmaxf(mrun0, nm0);
            nm1 = fmaxf(mrun1, nm1);
            const float al0 = __expf(mrun0 - nm0);
            const float al1 = __expf(mrun1 - nm1);
            mrun0 = nm0; mrun1 = nm1;

            uint32_t ph[16], pl[16];
            float sum0 = 0.f, sum1 = 0.f;
#pragma unroll
            for (int j = 0; j < 8; ++j) {
                float p0 = __expf(s[j][0] - nm0);
                float p1 = __expf(s[j][1] - nm0);
                float p2 = __expf(s[j][2] - nm1);
                float p3 = __expf(s[j][3] - nm1);
                sum0 += p0 + p1; sum1 += p2 + p3;
                uint32_t h01, h23;
                PACK_BF2(h01, p0, p1);
                PACK_BF2(h23, p2, p3);
                ph[2 * j] = h01; ph[2 * j + 1] = h23;
                float l0 = p0 - __uint_as_float(h01 << 16);
                float l1 = p1 - __uint_as_float(h01 & 0xFFFF0000u);
                float l2 = p2 - __uint_as_float(h23 << 16);
                float l3 = p3 - __uint_as_float(h23 & 0xFFFF0000u);
                uint32_t q01, q23;
                PACK_BF2(q01, l0, l1);
                PACK_BF2(q23, l2, l3);
                pl[2 * j] = q01; pl[2 * j + 1] = q23;
            }
            sum0 += __shfl_xor_sync(0xffffffffu, sum0, 1);
            sum0 += __shfl_xor_sync(0xffffffffu, sum0, 2);
            sum1 += __shfl_xor_sync(0xffffffffu, sum1, 1);
            sum1 += __shfl_xor_sync(0xffffffffu, sum1, 2);
            lrun0 = lrun0 * al0 + sum0;
            lrun1 = lrun1 * al1 + sum1;
#pragma unroll
            for (int j = 0; j < 8; ++j) {
                o[j][0] *= al0; o[j][1] *= al0;
                o[j][2] *= al1; o[j][3] *= al1;
            }

            // ---- O += P V (split: 3 HMMA) ----
#pragma unroll
            for (int ks2 = 0; ks2 < 4; ++ks2) {
                const int cb = ks2 >> 1;
                const int c = (ks2 & 1) * 2 + lhalf;
                const uint32_t* ap = &ph[4 * ks2];
                const uint32_t* lp = &pl[4 * ks2];
#pragma unroll
                for (int bp = 0; bp < 4; ++bp) {
                    uint32_t vh[4], vl[4];
                    uint32_t va = st + 16384 + cb * 4096 + sw_off(bp * 16 + lrow, c);
                    LDSM4(vh[0], vh[1], vh[2], vh[3], va);
                    LDSM4(vl[0], vl[1], vl[2], vl[3], va + 8192);
#pragma unroll
                    for (int sub = 0; sub < 2; ++sub) {
                        float* cc2 = o[bp * 2 + sub];
                        MMA16816(cc2[0], cc2[1], cc2[2], cc2[3],
                                 ap[0], ap[1], ap[2], ap[3], vh[sub], vh[sub + 2]);
                        MMA16816(cc2[0], cc2[1], cc2[2], cc2[3],
                                 ap[0], ap[1], ap[2], ap[3], vl[sub], vl[sub + 2]);
                        MMA16816(cc2[0], cc2[1], cc2[2], cc2[3],
                                 lp[0], lp[1], lp[2], lp[3], vh[sub], vh[sub + 2]);
                    }
                }
            }
        }

        __syncthreads();
        if (kt + 2 < nkt) issue_kv(kt + 2, kt & 1);
        CP_COMMIT();
        CP_WAIT1();
        __syncthreads();
    }

    // ---- normalize + write split bf16 [t][C] ----
    const float inv0 = 1.f / lrun0, inv1 = 1.f / lrun1;
    const int b = bh >> 4, h = bh & 15;
    const size_t row0 = ((size_t)(b * TSEQ + q0 + r0w + g)) * CDIM + h * HDIM;
    const size_t row1 = row0 + 8 * CDIM;
#pragma unroll
    for (int j = 0; j < 8; ++j) {
        int col = j * 8 + qd * 2;
        float v0 = o[j][0] * inv0, v1 = o[j][1] * inv0;
        float v2 = o[j][2] * inv1, v3 = o[j][3] * inv1;
        __nv_bfloat16 h0, l0, h1, l1;
        split2(v0, h0, l0); split2(v1, h1, l1);
        *(uint32_t*)&g_Yhi[row0 + col] = pack_bf(h0, h1);
        *(uint32_t*)&g_Ylo[row0 + col] = pack_bf(l0, l1);
        split2(v2, h0, l0); split2(v3, h1, l1);
        *(uint32_t*)&g_Yhi[row1 + col] = pack_bf(h0, h1);
        *(uint32_t*)&g_Ylo[row1 + col] = pack_bf(l0, l1);
    }
}

// ---------------- launch ----------------------------------------------------
extern "C" void kernel_launch(void* const* d_in, const int* in_sizes, int n_in,
                              void* d_out, int out_size) {
    (void)in_sizes; (void)n_in; (void)out_size;
    const float* x      = (const float*)d_in[0];
    const float* w_attn = (const float*)d_in[1];
    const float* b_attn = (const float*)d_in[2];
    const float* w_proj = (const float*)d_in[3];
    const float* b_proj = (const float*)d_in[4];
    float* out = (float*)d_out;

    cudaFuncSetAttribute(mma_gemm<3 * CDIM, 0>,
                         cudaFuncAttributeMaxDynamicSharedMemorySize, SMEM_DYN);
    cudaFuncSetAttribute(mma_gemm<CDIM, 1>,
                         cudaFuncAttributeMaxDynamicSharedMemorySize, SMEM_DYN);
    cudaFuncSetAttribute(attn_mma,
                         cudaFuncAttributeMaxDynamicSharedMemorySize, ATT_SMEM);

    __nv_bfloat16 *xhi, *xlo, *whi, *wlo, *phi, *plo, *yhi, *ylo;
    cudaGetSymbolAddress((void**)&xhi, g_Xhi);
    cudaGetSymbolAddress((void**)&xlo, g_Xlo);
    cudaGetSymbolAddress((void**)&whi, g_Whi);
    cudaGetSymbolAddress((void**)&wlo, g_Wlo);
    cudaGetSymbolAddress((void**)&phi, g_Phi);
    cudaGetSymbolAddress((void**)&plo, g_Plo);
    cudaGetSymbolAddress((void**)&yhi, g_Yhi);
    cudaGetSymbolAddress((void**)&ylo, g_Ylo);

    // pre-pass: split x, transpose+split weights
    conv_split<<<(MTOT * CDIM / 4) / 256, 256>>>(x, xhi, xlo);
    trans_split<<<dim3(3 * CDIM / 32, CDIM / 32), dim3(32, 8)>>>(
        w_attn, whi, wlo, CDIM, 3 * CDIM);
    trans_split<<<dim3(CDIM / 32, CDIM / 32), dim3(32, 8)>>>(
        w_proj, phi, plo, CDIM, CDIM);

    // 1) QKV projection -> split bf16 Q/K (row) and V (transposed)
    mma_gemm<3 * CDIM, 0><<<dim3(3 * CDIM / 128, MTOT / 128), 256, SMEM_DYN>>>(
        xhi, xlo, whi, wlo, b_attn, nullptr);

    // 2) causal attention (tensor cores) -> g_Yhi/g_Ylo
    attn_mma<<<dim3(TSEQ / 128, BHT), 256, ATT_SMEM>>>();

    // 3) output projection -> d_out
    mma_gemm<CDIM, 1><<<dim3(CDIM / 128, MTOT / 128), 256, SMEM_DYN>>>(
        yhi, ylo, phi, plo, b_proj, out);
}